// round 14
// baseline (speedup 1.0000x reference)
#include <cuda_runtime.h>
#include <cuda_fp16.h>
#include <math.h>
#include <stdint.h>

// Problem constants
#define BD   8
#define TD   2048
#define DD   512
#define NTOT (BD * TD)     // 16384
#define KTOT 4096          // D * P
#define NKC  64            // K-chunks of 64 elements
#define NMT  128           // M-tiles of 128 rows
#define SEG  64
#define SEGLEN (TD / SEG)  // 32

// ---------------------------------------------------------------------------
// Scratch (device globals — no allocations allowed)
// ---------------------------------------------------------------------------
__device__ float g_z[(size_t)NTOT * DD];    // sigmoid(z logits)
__device__ float g_hbar[(size_t)NTOT * DD];
// Pre-swizzled B chunk tiles: [layer][nb(4)][kc(64)] 16KB each
__device__ __align__(128) __half g_bt_hi[5][(size_t)4 * 64 * 8192];
// Compressed 2:4 A tiles: [inst(2)][mt(128)][kc(64)] 8KB each
__device__ __align__(128) __half   g_A[2][(size_t)NMT * NKC * 4096];
// Reordered metadata tiles: 2KB per (mt,kc), laid out [lane][wm][mi][q] u32
__device__ __align__(128) uint8_t g_MM[2][(size_t)NMT * NKC * 2048];
// scan scratch
__device__ float g_scanA[BD * SEG * DD];
__device__ float g_scanB[BD * SEG * DD];
__device__ float g_scanH[BD * SEG * DD];

// ---------------------------------------------------------------------------
// helpers
// ---------------------------------------------------------------------------
__device__ __forceinline__ uint32_t smem_u32(const void* p) {
    uint32_t a;
    asm("{ .reg .u64 t; cvta.to.shared.u64 t, %1; cvt.u32.u64 %0, t; }"
        : "=r"(a) : "l"(p));
    return a;
}

#define SWZ(x) ((x) ^ (((x) >> 3) & 0x70))

__device__ __forceinline__ void mbar_init(uint32_t a, uint32_t cnt) {
    asm volatile("mbarrier.init.shared.b64 [%0], %1;" :: "r"(a), "r"(cnt) : "memory");
}

__device__ __forceinline__ void mbar_wait(uint32_t a, uint32_t ph) {
    asm volatile(
        "{\n\t.reg .pred P;\n\t"
        "W%=:\n\t"
        "mbarrier.try_wait.parity.acquire.cta.shared::cta.b64 P, [%0], %1, 0x989680;\n\t"
        "@P bra.uni D%=;\n\t"
        "bra.uni W%=;\n\t"
        "D%=:\n\t}"
        :: "r"(a), "r"(ph) : "memory");
}

__device__ __forceinline__ void mbar_expect_tx(uint32_t a, uint32_t bytes) {
    asm volatile("mbarrier.arrive.expect_tx.shared.b64 _, [%0], %1;"
                 :: "r"(a), "r"(bytes) : "memory");
}

__device__ __forceinline__ void bulk_ld(uint32_t dst, const void* src,
                                        uint32_t bytes, uint32_t mbar) {
    asm volatile(
        "cp.async.bulk.shared::cluster.global.mbarrier::complete_tx::bytes "
        "[%0], [%1], %2, [%3];"
        :: "r"(dst), "l"(src), "r"(bytes), "r"(mbar) : "memory");
}

// 2:4 compression of the hat pair (1-t @ k, t @ k+1) within an 8-wide i-block.
__device__ __forceinline__ void hat_compress(float x, const float* p,
                                             uint32_t& w0, uint32_t& w1,
                                             uint32_t& mb) {
    int k = 0;
    float pl = p[0], pr = p[1];
#pragma unroll
    for (int j = 1; j <= 6; ++j)
        if (p[j] < x) { k = j; pl = p[j]; pr = p[j + 1]; }
    float t = fminf(fmaxf((x - pl) / (pr - pl), 0.0f), 1.0f);
    __half2 h2 = __floats2half2_rn(1.0f - t, t);
    uint32_t P = *(uint32_t*)&h2;
    uint32_t m0, m1;
    if (k <= 2)      { w0 = P;       w1 = 0u;      m0 = (uint32_t)(k | ((k + 1) << 2)); m1 = 4u; }
    else if (k == 3) { w0 = P << 16; w1 = P >> 16; m0 = 12u;                            m1 = 4u; }
    else             { int kp = k - 4; w0 = 0u; w1 = P; m0 = 4u;
                       m1 = (uint32_t)(kp | ((kp + 1) << 2)); }
    mb = m0 | (m1 << 4);
}

// Byte offset of meta(n, il) inside the reordered 2KB tile (dup = lane&2 copy).
// Layout: word index = ((lane*2 + wm)*4 + mi)*2 + q; byte = ib + hi*2.
__device__ __forceinline__ uint32_t meta_off(int n, int il, int dup) {
    int wm = n >> 6, mi = (n >> 4) & 3, r8 = n & 15;
    int rlow = r8 & 7, hi = r8 >> 3;
    int q = il >> 2, b01 = (il >> 1) & 1, ib = il & 1;
    int lane = rlow * 4 + b01 + dup * 2;
    return (uint32_t)((((lane * 2 + wm) * 4 + mi) * 2 + q) * 4 + ib + hi * 2);
}

// ---------------------------------------------------------------------------
// split_chunk: v (4096 x 512 f32) -> pre-swizzled 16KB B chunk tiles, fp16.
// ---------------------------------------------------------------------------
__global__ __launch_bounds__(256) void split_chunk_kernel(
    const float* __restrict__ va, const float* __restrict__ vb,
    const float* __restrict__ vc, int ibase) {
    int kc = blockIdx.x, nb = blockIdx.y, z = blockIdx.z;
    const float* v = (z == 0) ? va : (z == 1) ? vb : vc;
    int layer = ibase + z;
    size_t tile_off = ((size_t)layer * 256 + nb * 64 + kc) << 14;  // bytes
    char* hib = (char*)g_bt_hi + tile_off;

    int r = threadIdx.x & 127;
    int chalf = threadIdx.x >> 7;
#pragma unroll
    for (int j = 0; j < 32; ++j) {
        int c = chalf * 32 + j;
        float val = v[(size_t)(kc * 64 + c) * DD + nb * 128 + r];
        uint32_t off = SWZ((uint32_t)(r * 128 + c * 2));
        *(__half*)(hib + off) = __float2half_rn(val);
    }
}

// ---------------------------------------------------------------------------
// build_A_kernel (layer 0 only, from input x)
// ---------------------------------------------------------------------------
__global__ __launch_bounds__(256) void build_A_kernel(
    const float* __restrict__ X, const float* __restrict__ P0,
    const float* __restrict__ P1) {
    int mt = blockIdx.x, kc = blockIdx.y, z = blockIdx.z;
    const float* Pp = z ? P1 : P0;
    char* Ab = (char*)g_A[z] + ((size_t)(mt * NKC + kc) << 13);
    uint8_t* Mb = g_MM[z] + ((size_t)(mt * NKC + kc) << 11);
    int tid = threadIdx.x;
    int il = tid & 7;
    int i = kc * 8 + il;
    float p[8];
#pragma unroll
    for (int j = 0; j < 8; ++j) p[j] = __ldg(&Pp[i * 8 + j]);
    int bm = mt * 128;
#pragma unroll
    for (int q = 0; q < 4; ++q) {
        int n = (tid >> 3) + 32 * q;
        float x = __ldg(&X[(size_t)(bm + n) * DD + i]);
        uint32_t w0, w1, mb;
        hat_compress(x, p, w0, w1, mb);
        uint32_t off = (uint32_t)((n >> 1) * 128 + (n & 1) * 64 +
                                  (il >> 2) * 32 + (il & 3) * 8);
        *(uint2*)(Ab + SWZ(off)) = make_uint2(w0, w1);
        Mb[meta_off(n, il, 0)] = (uint8_t)mb;
        Mb[meta_off(n, il, 1)] = (uint8_t)mb;
    }
}

// ---------------------------------------------------------------------------
// APL sparse-HMMA GEMM. 4-stage bulk-DMA ring of [A 8K][meta 2K][B 16K].
// 256 threads, 8 warps (2Mx4N), warp tile 64x32, CTA 128x128, 2 CTA/SM.
// ---------------------------------------------------------------------------
#define STAGE_SZ 26624
#define SMEM_REQ (1024 + 1024 + 4 * STAGE_SZ)

__device__ __forceinline__ void ldsm4(uint32_t a, uint32_t& r0, uint32_t& r1,
                                      uint32_t& r2, uint32_t& r3) {
    asm volatile("ldmatrix.sync.aligned.m8n8.x4.shared.b16 {%0,%1,%2,%3}, [%4];"
                 : "=r"(r0), "=r"(r1), "=r"(r2), "=r"(r3) : "r"(a));
}

__device__ __forceinline__ void mmasp(float* d, const uint32_t* a,
                                      const uint32_t* b, uint32_t e) {
    asm volatile(
        "mma.sp::ordered_metadata.sync.aligned.m16n8k32.row.col.f32.f16.f16.f32 "
        "{%0,%1,%2,%3}, {%4,%5,%6,%7}, {%8,%9,%10,%11}, {%0,%1,%2,%3}, %12, 0x0;"
        : "+f"(d[0]), "+f"(d[1]), "+f"(d[2]), "+f"(d[3])
        : "r"(a[0]), "r"(a[1]), "r"(a[2]), "r"(a[3]),
          "r"(b[0]), "r"(b[1]), "r"(b[2]), "r"(b[3]), "r"(e));
}

__global__ void __launch_bounds__(256, 2) apl_hmma_kernel(
    const __half* __restrict__ A0, const uint8_t* __restrict__ M0,
    const __half* __restrict__ A1, const uint8_t* __restrict__ M1,
    const __half* __restrict__ B0, const __half* __restrict__ B1,
    float* __restrict__ out0, float* __restrict__ out1, int sigz) {
    const int zz = blockIdx.z;
    const char* aSrc = (const char*)(zz ? A1 : A0);
    const char* mSrc = (const char*)(zz ? M1 : M0);
    const __half* Bhi = zz ? B1 : B0;
    float* out = zz ? out1 : out0;
    const int dosig = sigz && (zz == 0);

    extern __shared__ char smem[];
    uint32_t sb = (smem_u32(smem) + 1023u) & ~1023u;
    const uint32_t MB = sb;
    const uint32_t ST = sb + 1024;
    const int tid = threadIdx.x;
    const int lane = tid & 31;
    const int wid = tid >> 5;
    const int wm = wid & 1;
    const int wn = wid >> 1;
    const int mt = blockIdx.x;
    const int nb = blockIdx.y;

    const char* bsrc = (const char*)Bhi + ((size_t)nb * 64 << 14);
    const size_t atile0 = (size_t)mt * NKC;

    if (tid == 0) {
        mbar_init(MB + 0, 1);
        mbar_init(MB + 8, 1);
        mbar_init(MB + 16, 1);
        mbar_init(MB + 24, 1);
        asm volatile("fence.proxy.async.shared::cta;" ::: "memory");
    }
    __syncthreads();

    float acc[4][4][4];
#pragma unroll
    for (int mi = 0; mi < 4; ++mi)
#pragma unroll
        for (int nj = 0; nj < 4; ++nj)
#pragma unroll
            for (int u = 0; u < 4; ++u) acc[mi][nj][u] = 0.0f;

    // hoisted, fully swizzled per-thread offsets (loop-invariant)
    uint32_t swa[4][2], swb[2][4];
#pragma unroll
    for (int mi = 0; mi < 4; ++mi) {
        int arow = wm * 64 + mi * 16 + (lane & 15);
        uint32_t base = (uint32_t)((arow >> 1) * 128 + (arow & 1) * 64 +
                                   (lane >> 4) * 16);
#pragma unroll
        for (int q = 0; q < 2; ++q) swa[mi][q] = SWZ(base + q * 32);
    }
#pragma unroll
    for (int ni = 0; ni < 2; ++ni) {
        int row = wn * 32 + ni * 16 + (lane & 7) + ((lane & 16) >> 1);
        uint32_t base = (uint32_t)(row * 128 + ((lane >> 3) & 1) * 16);
#pragma unroll
        for (int k4 = 0; k4 < 4; ++k4) swb[ni][k4] = SWZ(base + k4 * 32);
    }
    const uint32_t me_base = (uint32_t)((lane * 2 + wm) * 32);

    if (tid == 0) {
#pragma unroll
        for (int c = 0; c < 3; ++c) {
            uint32_t stb = ST + c * STAGE_SZ;
            mbar_expect_tx(MB + c * 8, STAGE_SZ);
            bulk_ld(stb, aSrc + ((atile0 + c) << 13), 8192, MB + c * 8);
            bulk_ld(stb + 8192, mSrc + ((atile0 + c) << 11), 2048, MB + c * 8);
            bulk_ld(stb + 10240, bsrc + ((size_t)c << 14), 16384, MB + c * 8);
        }
    }

    for (int kc = 0; kc < NKC; ++kc) {
        int st = kc & 3;
        uint32_t parity = (uint32_t)((kc >> 2) & 1);
        mbar_wait(MB + st * 8, parity);
        __syncthreads();

        if (tid == 0 && kc + 3 < NKC) {
            int s2 = (kc + 3) & 3;
            uint32_t stb = ST + s2 * STAGE_SZ;
            mbar_expect_tx(MB + s2 * 8, STAGE_SZ);
            bulk_ld(stb, aSrc + ((atile0 + kc + 3) << 13), 8192, MB + s2 * 8);
            bulk_ld(stb + 8192, mSrc + ((atile0 + kc + 3) << 11), 2048, MB + s2 * 8);
            bulk_ld(stb + 10240, bsrc + ((size_t)(kc + 3) << 14), 16384, MB + s2 * 8);
        }

        const uint32_t AHc = ST + st * STAGE_SZ;
        const uint32_t MEc = AHc + 8192;
        const uint32_t BHc = AHc + 10240;

        // metadata: 2 vector loads, zero merge ALU. mr[mi*2+q].
        uint32_t mr[8];
        asm volatile("ld.shared.v4.b32 {%0,%1,%2,%3}, [%4];"
                     : "=r"(mr[0]), "=r"(mr[1]), "=r"(mr[2]), "=r"(mr[3])
                     : "r"(MEc + me_base));
        asm volatile("ld.shared.v4.b32 {%0,%1,%2,%3}, [%4];"
                     : "=r"(mr[4]), "=r"(mr[5]), "=r"(mr[6]), "=r"(mr[7])
                     : "r"(MEc + me_base + 16));

#pragma unroll
        for (int q = 0; q < 2; ++q) {
            uint32_t asp[4][4], bsp[4][4];
#pragma unroll
            for (int mi = 0; mi < 4; ++mi)
                ldsm4(AHc + swa[mi][q],
                      asp[mi][0], asp[mi][1], asp[mi][2], asp[mi][3]);
#pragma unroll
            for (int ni = 0; ni < 2; ++ni) {
                uint32_t r0, r1, r2, r3;
                ldsm4(BHc + swb[ni][2 * q], r0, r1, r2, r3);
                bsp[2 * ni][0] = r0; bsp[2 * ni][1] = r1;
                bsp[2 * ni + 1][0] = r2; bsp[2 * ni + 1][1] = r3;
                ldsm4(BHc + swb[ni][2 * q + 1], r0, r1, r2, r3);
                bsp[2 * ni][2] = r0; bsp[2 * ni][3] = r1;
                bsp[2 * ni + 1][2] = r2; bsp[2 * ni + 1][3] = r3;
            }
#pragma unroll
            for (int mi = 0; mi < 4; ++mi)
#pragma unroll
                for (int nj = 0; nj < 4; ++nj)
                    mmasp(acc[mi][nj], asp[mi], bsp[nj], mr[mi * 2 + q]);
        }
    }

    // epilogue (optional fused sigmoid for the z instance)
#pragma unroll
    for (int mi = 0; mi < 4; ++mi) {
#pragma unroll
        for (int nj = 0; nj < 4; ++nj) {
            float v0 = acc[mi][nj][0], v1 = acc[mi][nj][1];
            float v2 = acc[mi][nj][2], v3 = acc[mi][nj][3];
            if (dosig) {
                v0 = 1.0f / (1.0f + __expf(-v0));
                v1 = 1.0f / (1.0f + __expf(-v1));
                v2 = 1.0f / (1.0f + __expf(-v2));
                v3 = 1.0f / (1.0f + __expf(-v3));
            }
            int row = mt * 128 + wm * 64 + mi * 16 + (lane >> 2);
            int col = nb * 128 + wn * 32 + nj * 8 + 2 * (lane & 3);
            *(float2*)&out[(size_t)row * DD + col] = make_float2(v0, v1);
            *(float2*)&out[(size_t)(row + 8) * DD + col] = make_float2(v2, v3);
        }
    }
}

// ---------------------------------------------------------------------------
// Segmented scan, SEG=64 (z already sigmoided). p1/p2 vectorized float4.
// ---------------------------------------------------------------------------
__global__ __launch_bounds__(256) void scan_p1(
    const float4* __restrict__ z4, const float4* __restrict__ hb4) {
    int gid = blockIdx.x * blockDim.x + threadIdx.x;   // 0 .. BD*SEG*128-1
    if (gid >= BD * SEG * (DD / 4)) return;
    int d4 = gid & 127;
    int bs = gid >> 7;
    int seg = bs & (SEG - 1);
    int b = bs / SEG;
    size_t base = ((size_t)b * TD * DD + (size_t)seg * SEGLEN * DD) / 4 + d4;
    float4 A = make_float4(1.f, 1.f, 1.f, 1.f);
    float4 Bv = make_float4(0.f, 0.f, 0.f, 0.f);
#pragma unroll 4
    for (int t = 0; t < SEGLEN; ++t) {
        size_t idx = base + (size_t)t * (DD / 4);
        float4 zv = z4[idx];
        float4 hv = hb4[idx];
        float ax = 1.f - zv.x, ay = 1.f - zv.y, az = 1.f - zv.z, aw = 1.f - zv.w;
        A.x *= ax; A.y *= ay; A.z *= az; A.w *= aw;
        Bv.x = fmaf(ax, Bv.x, zv.x * hv.x);
        Bv.y = fmaf(ay, Bv.y, zv.y * hv.y);
        Bv.z = fmaf(az, Bv.z, zv.z * hv.z);
        Bv.w = fmaf(aw, Bv.w, zv.w * hv.w);
    }
    ((float4*)g_scanA)[gid] = A;
    ((float4*)g_scanB)[gid] = Bv;
}

__global__ __launch_bounds__(256) void scan_p2() {
    int c = blockIdx.x * blockDim.x + threadIdx.x;   // 0 .. BD*128-1
    if (c >= BD * (DD / 4)) return;
    int d4 = c & 127;
    int b = c >> 7;
    float4 h = make_float4(0.f, 0.f, 0.f, 0.f);
#pragma unroll
    for (int seg = 0; seg < SEG; ++seg) {
        int gid = (b * SEG + seg) * 128 + d4;
        ((float4*)g_scanH)[gid] = h;
        float4 A = ((float4*)g_scanA)[gid];
        float4 Bv = ((float4*)g_scanB)[gid];
        h.x = fmaf(A.x, h.x, Bv.x);
        h.y = fmaf(A.y, h.y, Bv.y);
        h.z = fmaf(A.z, h.z, Bv.z);
        h.w = fmaf(A.w, h.w, Bv.w);
    }
}

// p3 + maxabs norm + FUSED next-layer compressed-A build (nsets param sets).
// block = 512 threads = all d of one (b, seg).
__global__ __launch_bounds__(512) void scan_p3_norm_fuse(
    const float* __restrict__ z, const float* __restrict__ hb,
    float* __restrict__ h, const float* __restrict__ P0,
    const float* __restrict__ P1, int nsets) {
    __shared__ float red[34];
    int blk = blockIdx.x;
    int d = threadIdx.x;
    int seg = blk & (SEG - 1);
    int b = blk / SEG;
    int lane = d & 31, wid = d >> 5;
    size_t base = (size_t)b * TD * DD + (size_t)seg * SEGLEN * DD + d;
    float hc = g_scanH[(blk << 9) + d];

    float p0[8], p1[8];
#pragma unroll
    for (int j = 0; j < 8; ++j) p0[j] = __ldg(&P0[d * 8 + j]);
    if (nsets > 1) {
#pragma unroll
        for (int j = 0; j < 8; ++j) p1[j] = __ldg(&P1[d * 8 + j]);
    }
    const int il = d & 7;
    const int kc = d >> 3;
    const int n0g = b * TD + seg * SEGLEN;
    const int mt = n0g >> 7;
    const int nnb = n0g & 127;
    char* Ab0 = (char*)g_A[0] + ((size_t)(mt * NKC + kc) << 13);
    uint8_t* Mb0 = g_MM[0] + ((size_t)(mt * NKC + kc) << 11);
    char* Ab1 = (char*)g_A[1] + ((size_t)(mt * NKC + kc) << 13);
    uint8_t* Mb1 = g_MM[1] + ((size_t)(mt * NKC + kc) << 11);
    const uint32_t ilo = (uint32_t)((il >> 2) * 32 + (il & 3) * 8);

    for (int t = 0; t < SEGLEN; ++t) {
        size_t idx = base + (size_t)t * DD;
        float zv = z[idx];
        hc = fmaf(zv, hb[idx] - hc, hc);
        int slot = (t & 1) * 17;
        float m = fabsf(hc);
#pragma unroll
        for (int o = 16; o; o >>= 1)
            m = fmaxf(m, __shfl_xor_sync(0xffffffffu, m, o));
        if (lane == 0) red[slot + wid] = m;
        __syncthreads();
        if (wid == 0) {
            float mm = red[slot + (lane & 15)];
#pragma unroll
            for (int o = 8; o; o >>= 1)
                mm = fmaxf(mm, __shfl_xor_sync(0xffffffffu, mm, o));
            if (lane == 0) red[slot + 16] = mm;
        }
        __syncthreads();
        float inv = 1.0f / (red[slot + 16] + 1e-6f);
        float hn = hc * inv;
        h[idx] = hn;

        int nn = nnb + t;
        uint32_t aoff = SWZ((uint32_t)((nn >> 1) * 128 + (nn & 1) * 64) + ilo);
        uint32_t w0, w1, mb;
        hat_compress(hn, p0, w0, w1, mb);
        *(uint2*)(Ab0 + aoff) = make_uint2(w0, w1);
        Mb0[meta_off(nn, il, 0)] = (uint8_t)mb;
        Mb0[meta_off(nn, il, 1)] = (uint8_t)mb;
        if (nsets > 1) {
            hat_compress(hn, p1, w0, w1, mb);
            *(uint2*)(Ab1 + aoff) = make_uint2(w0, w1);
            Mb1[meta_off(nn, il, 0)] = (uint8_t)mb;
            Mb1[meta_off(nn, il, 1)] = (uint8_t)mb;
        }
    }
}

// ---------------------------------------------------------------------------
// kernel_launch (launch #4 = paired apl_hmma for the ncu capture window)
// ---------------------------------------------------------------------------
extern "C" void kernel_launch(void* const* d_in, const int* in_sizes, int n_in,
                              void* d_out, int out_size) {
    const float* x   = (const float*)d_in[0];
    const float* pz0 = (const float*)d_in[1];
    const float* vz0 = (const float*)d_in[2];
    const float* ph0 = (const float*)d_in[3];
    const float* vh0 = (const float*)d_in[4];
    const float* pz1 = (const float*)d_in[5];
    const float* vz1 = (const float*)d_in[6];
    const float* ph1 = (const float*)d_in[7];
    const float* vh1 = (const float*)d_in[8];
    const float* po  = (const float*)d_in[9];
    const float* vo  = (const float*)d_in[10];

    const int N = in_sizes[0] / DD;  // 16384

    float *zb, *hb;
    __half *bhi, *a0, *a1;
    uint8_t *m0, *m1;
    cudaGetSymbolAddress((void**)&zb, g_z);
    cudaGetSymbolAddress((void**)&hb, g_hbar);
    cudaGetSymbolAddress((void**)&bhi, g_bt_hi);
    cudaGetSymbolAddress((void**)&a0, g_A);
    cudaGetSymbolAddress((void**)&m0, g_MM);
    a1 = a0 + (size_t)NMT * NKC * 4096;
    m1 = m0 + (size_t)NMT * NKC * 2048;

    static int smem_set = 0;
    if (!smem_set) {
        cudaFuncSetAttribute(apl_hmma_kernel,
                             cudaFuncAttributeMaxDynamicSharedMemorySize, SMEM_REQ);
        smem_set = 1;
    }

    float* out = (float*)d_out;
    float* h1  = out + (size_t)N * DD;
    float* h2  = h1 + (size_t)N * DD;

    dim3 sp3(64, 4, 3);
    dim3 sp2(64, 4, 2);
    dim3 agrid2(NMT, NKC, 2);
    dim3 gpair(NMT, 4, 2);
    dim3 gone(NMT, 4, 1);
    const int p1_blocks = (BD * SEG * (DD / 4) + 255) / 256;
    const int p2_blocks = (BD * (DD / 4) + 255) / 256;
    const int p3_blocks = BD * SEG;
    const size_t LSZ = (size_t)4 * 64 * 8192;

    // [1][2] pre-stage all V into chunked/pre-swizzled fp16 B tiles
    split_chunk_kernel<<<sp3, 256>>>(vz0, vh0, vz1, 0);
    split_chunk_kernel<<<sp2, 256>>>(vh1, vo, vo, 3);

    // ---- layer 0 ----
    build_A_kernel<<<agrid2, 256>>>(x, pz0, ph0);                            // [3]
    apl_hmma_kernel<<<gpair, 256, SMEM_REQ>>>(a0, m0, a1, m1,
                                              bhi + 0 * LSZ, bhi + 1 * LSZ,
                                              zb, hb, 1);                    // [4] profiled
    scan_p1<<<p1_blocks, 256>>>((const float4*)zb, (const float4*)hb);
    scan_p2<<<p2_blocks, 256>>>();
    scan_p3_norm_fuse<<<p3_blocks, 512>>>(zb, hb, h1, pz1, ph1, 2);

    // ---- layer 1 (A tiles built by fused p3) ----
    apl_hmma_kernel<<<gpair, 256, SMEM_REQ>>>(a0, m0, a1, m1,
                                              bhi + 2 * LSZ, bhi + 3 * LSZ,
                                              zb, hb, 1);
    scan_p1<<<p1_blocks, 256>>>((const float4*)zb, (const float4*)hb);
    scan_p2<<<p2_blocks, 256>>>();
    scan_p3_norm_fuse<<<p3_blocks, 512>>>(zb, hb, h2, po, po, 1);

    // ---- output APL (A tiles built by fused p3) ----
    apl_hmma_kernel<<<gone, 256, SMEM_REQ>>>(a0, m0, a0, m0,
                                             bhi + 4 * LSZ, bhi + 4 * LSZ,
                                             out, out, 0);
}

// round 15
// speedup vs baseline: 1.0682x; 1.0682x over previous
#include <cuda_runtime.h>
#include <cuda_fp16.h>
#include <math.h>
#include <stdint.h>

// Problem constants
#define BD   8
#define TD   2048
#define DD   512
#define NTOT (BD * TD)     // 16384
#define KTOT 4096          // D * P
#define NKC  64            // K-chunks of 64 elements
#define NMT  128           // M-tiles of 128 rows
#define SEG  64
#define SEGLEN (TD / SEG)  // 32

// ---------------------------------------------------------------------------
// Scratch (device globals — no allocations allowed)
// ---------------------------------------------------------------------------
__device__ float g_z[(size_t)NTOT * DD];    // sigmoid(z logits)
__device__ float g_hbar[(size_t)NTOT * DD];
// Pre-swizzled B chunk tiles: [layer][nb(4)][kc(64)] 16KB each
__device__ __align__(128) __half g_bt_hi[5][(size_t)4 * 64 * 8192];
// Compressed 2:4 A tiles: [inst(2)][mt(128)][kc(64)] 8KB each
__device__ __align__(128) __half   g_A[2][(size_t)NMT * NKC * 4096];
// Reordered metadata: 2KB per (mt,kc); word idx = lane + 32*(wm*8+mi*2+q)
__device__ __align__(128) uint8_t g_MM[2][(size_t)NMT * NKC * 2048];
// scan scratch
__device__ float g_scanA[BD * SEG * DD];
__device__ float g_scanB[BD * SEG * DD];
__device__ float g_scanH[BD * SEG * DD];

// ---------------------------------------------------------------------------
// helpers
// ---------------------------------------------------------------------------
__device__ __forceinline__ uint32_t smem_u32(const void* p) {
    uint32_t a;
    asm("{ .reg .u64 t; cvta.to.shared.u64 t, %1; cvt.u32.u64 %0, t; }"
        : "=r"(a) : "l"(p));
    return a;
}

#define SWZ(x) ((x) ^ (((x) >> 3) & 0x70))

__device__ __forceinline__ void mbar_init(uint32_t a, uint32_t cnt) {
    asm volatile("mbarrier.init.shared.b64 [%0], %1;" :: "r"(a), "r"(cnt) : "memory");
}

__device__ __forceinline__ void mbar_wait(uint32_t a, uint32_t ph) {
    asm volatile(
        "{\n\t.reg .pred P;\n\t"
        "W%=:\n\t"
        "mbarrier.try_wait.parity.acquire.cta.shared::cta.b64 P, [%0], %1, 0x989680;\n\t"
        "@P bra.uni D%=;\n\t"
        "bra.uni W%=;\n\t"
        "D%=:\n\t}"
        :: "r"(a), "r"(ph) : "memory");
}

__device__ __forceinline__ void mbar_expect_tx(uint32_t a, uint32_t bytes) {
    asm volatile("mbarrier.arrive.expect_tx.shared.b64 _, [%0], %1;"
                 :: "r"(a), "r"(bytes) : "memory");
}

__device__ __forceinline__ void bulk_ld(uint32_t dst, const void* src,
                                        uint32_t bytes, uint32_t mbar) {
    asm volatile(
        "cp.async.bulk.shared::cluster.global.mbarrier::complete_tx::bytes "
        "[%0], [%1], %2, [%3];"
        :: "r"(dst), "l"(src), "r"(bytes), "r"(mbar) : "memory");
}

// 2:4 compression of the hat pair (1-t @ k, t @ k+1) within an 8-wide i-block.
__device__ __forceinline__ void hat_compress(float x, const float* p,
                                             uint32_t& w0, uint32_t& w1,
                                             uint32_t& mb) {
    int k = 0;
    float pl = p[0], pr = p[1];
#pragma unroll
    for (int j = 1; j <= 6; ++j)
        if (p[j] < x) { k = j; pl = p[j]; pr = p[j + 1]; }
    float t = fminf(fmaxf((x - pl) / (pr - pl), 0.0f), 1.0f);
    __half2 h2 = __floats2half2_rn(1.0f - t, t);
    uint32_t P = *(uint32_t*)&h2;
    uint32_t m0, m1;
    if (k <= 2)      { w0 = P;       w1 = 0u;      m0 = (uint32_t)(k | ((k + 1) << 2)); m1 = 4u; }
    else if (k == 3) { w0 = P << 16; w1 = P >> 16; m0 = 12u;                            m1 = 4u; }
    else             { int kp = k - 4; w0 = 0u; w1 = P; m0 = 4u;
                       m1 = (uint32_t)(kp | ((kp + 1) << 2)); }
    mb = m0 | (m1 << 4);
}

// Byte offset of meta(n, il) inside the reordered 2KB tile (dup = copy 0/1).
// word idx = lane + 32*(wm*8 + mi*2 + q); byte-in-word = ib + hi*2.
__device__ __forceinline__ uint32_t meta_off(int n, int il, int dup) {
    int wm = n >> 6, mi = (n >> 4) & 3, r8 = n & 15;
    int rlow = r8 & 7, hi = r8 >> 3;
    int q = il >> 2, b01 = (il >> 1) & 1, ib = il & 1;
    int lane = rlow * 4 + b01 + dup * 2;
    return (uint32_t)((lane + 32 * (wm * 8 + mi * 2 + q)) * 4 + ib + hi * 2);
}

// ---------------------------------------------------------------------------
// split_chunk: v (4096 x 512 f32) -> pre-swizzled 16KB B chunk tiles, fp16.
// ---------------------------------------------------------------------------
__global__ __launch_bounds__(256) void split_chunk_kernel(
    const float* __restrict__ va, const float* __restrict__ vb,
    const float* __restrict__ vc, int ibase) {
    int kc = blockIdx.x, nb = blockIdx.y, z = blockIdx.z;
    const float* v = (z == 0) ? va : (z == 1) ? vb : vc;
    int layer = ibase + z;
    size_t tile_off = ((size_t)layer * 256 + nb * 64 + kc) << 14;  // bytes
    char* hib = (char*)g_bt_hi + tile_off;

    int r = threadIdx.x & 127;
    int chalf = threadIdx.x >> 7;
#pragma unroll
    for (int j = 0; j < 32; ++j) {
        int c = chalf * 32 + j;
        float val = v[(size_t)(kc * 64 + c) * DD + nb * 128 + r];
        uint32_t off = SWZ((uint32_t)(r * 128 + c * 2));
        *(__half*)(hib + off) = __float2half_rn(val);
    }
}

// ---------------------------------------------------------------------------
// build_A_kernel (layer 0 only, from input x)
// ---------------------------------------------------------------------------
__global__ __launch_bounds__(256) void build_A_kernel(
    const float* __restrict__ X, const float* __restrict__ P0,
    const float* __restrict__ P1) {
    int mt = blockIdx.x, kc = blockIdx.y, z = blockIdx.z;
    const float* Pp = z ? P1 : P0;
    char* Ab = (char*)g_A[z] + ((size_t)(mt * NKC + kc) << 13);
    uint8_t* Mb = g_MM[z] + ((size_t)(mt * NKC + kc) << 11);
    int tid = threadIdx.x;
    int il = tid & 7;
    int i = kc * 8 + il;
    float p[8];
#pragma unroll
    for (int j = 0; j < 8; ++j) p[j] = __ldg(&Pp[i * 8 + j]);
    int bm = mt * 128;
#pragma unroll
    for (int q = 0; q < 4; ++q) {
        int n = (tid >> 3) + 32 * q;
        float x = __ldg(&X[(size_t)(bm + n) * DD + i]);
        uint32_t w0, w1, mb;
        hat_compress(x, p, w0, w1, mb);
        uint32_t off = (uint32_t)((n >> 1) * 128 + (n & 1) * 64 +
                                  (il >> 2) * 32 + (il & 3) * 8);
        *(uint2*)(Ab + SWZ(off)) = make_uint2(w0, w1);
        Mb[meta_off(n, il, 0)] = (uint8_t)mb;
        Mb[meta_off(n, il, 1)] = (uint8_t)mb;
    }
}

// ---------------------------------------------------------------------------
// APL sparse-HMMA GEMM. 4-stage bulk-DMA ring of [A 8K][meta 2K][B 16K].
// 256 threads, 8 warps (2Mx4N), warp tile 64x32, CTA 128x128, 2 CTA/SM.
// ---------------------------------------------------------------------------
#define STAGE_SZ 26624
#define SMEM_REQ (1024 + 1024 + 4 * STAGE_SZ)

__device__ __forceinline__ void ldsm4(uint32_t a, uint32_t& r0, uint32_t& r1,
                                      uint32_t& r2, uint32_t& r3) {
    asm volatile("ldmatrix.sync.aligned.m8n8.x4.shared.b16 {%0,%1,%2,%3}, [%4];"
                 : "=r"(r0), "=r"(r1), "=r"(r2), "=r"(r3) : "r"(a));
}

__device__ __forceinline__ void mmasp(float* d, const uint32_t* a,
                                      const uint32_t* b, uint32_t e) {
    asm volatile(
        "mma.sp::ordered_metadata.sync.aligned.m16n8k32.row.col.f32.f16.f16.f32 "
        "{%0,%1,%2,%3}, {%4,%5,%6,%7}, {%8,%9,%10,%11}, {%0,%1,%2,%3}, %12, 0x0;"
        : "+f"(d[0]), "+f"(d[1]), "+f"(d[2]), "+f"(d[3])
        : "r"(a[0]), "r"(a[1]), "r"(a[2]), "r"(a[3]),
          "r"(b[0]), "r"(b[1]), "r"(b[2]), "r"(b[3]), "r"(e));
}

__global__ void __launch_bounds__(256, 2) apl_hmma_kernel(
    const __half* __restrict__ A0, const uint8_t* __restrict__ M0,
    const __half* __restrict__ A1, const uint8_t* __restrict__ M1,
    const __half* __restrict__ B0, const __half* __restrict__ B1,
    float* __restrict__ out0, float* __restrict__ out1, int sigz) {
    const int zz = blockIdx.z;
    const char* aSrc = (const char*)(zz ? A1 : A0);
    const char* mSrc = (const char*)(zz ? M1 : M0);
    const __half* Bhi = zz ? B1 : B0;
    float* out = zz ? out1 : out0;
    const int dosig = sigz && (zz == 0);

    extern __shared__ char smem[];
    uint32_t sb = (smem_u32(smem) + 1023u) & ~1023u;
    const uint32_t MB = sb;
    const uint32_t ST = sb + 1024;
    const int tid = threadIdx.x;
    const int lane = tid & 31;
    const int wid = tid >> 5;
    const int wm = wid & 1;
    const int wn = wid >> 1;
    const int mt = blockIdx.x;
    const int nb = blockIdx.y;

    const char* bsrc = (const char*)Bhi + ((size_t)nb * 64 << 14);
    const size_t atile0 = (size_t)mt * NKC;

    if (tid == 0) {
        mbar_init(MB + 0, 1);
        mbar_init(MB + 8, 1);
        mbar_init(MB + 16, 1);
        mbar_init(MB + 24, 1);
        asm volatile("fence.proxy.async.shared::cta;" ::: "memory");
    }
    __syncthreads();

    float acc[4][4][4];
#pragma unroll
    for (int mi = 0; mi < 4; ++mi)
#pragma unroll
        for (int nj = 0; nj < 4; ++nj)
#pragma unroll
            for (int u = 0; u < 4; ++u) acc[mi][nj][u] = 0.0f;

    // hoisted, fully swizzled per-thread offsets (loop-invariant)
    uint32_t swa[4][2], swb[2][4];
#pragma unroll
    for (int mi = 0; mi < 4; ++mi) {
        int arow = wm * 64 + mi * 16 + (lane & 15);
        uint32_t base = (uint32_t)((arow >> 1) * 128 + (arow & 1) * 64 +
                                   (lane >> 4) * 16);
#pragma unroll
        for (int q = 0; q < 2; ++q) swa[mi][q] = SWZ(base + q * 32);
    }
#pragma unroll
    for (int ni = 0; ni < 2; ++ni) {
        int row = wn * 32 + ni * 16 + (lane & 7) + ((lane & 16) >> 1);
        uint32_t base = (uint32_t)(row * 128 + ((lane >> 3) & 1) * 16);
#pragma unroll
        for (int k4 = 0; k4 < 4; ++k4) swb[ni][k4] = SWZ(base + k4 * 32);
    }
    // per-thread metadata byte base: lane*4 + wm*1024; word (mi*2+q) at +128 each
    const uint32_t me_base = (uint32_t)(lane * 4 + wm * 1024);

    if (tid == 0) {
#pragma unroll
        for (int c = 0; c < 3; ++c) {
            uint32_t stb = ST + c * STAGE_SZ;
            mbar_expect_tx(MB + c * 8, STAGE_SZ);
            bulk_ld(stb, aSrc + ((atile0 + c) << 13), 8192, MB + c * 8);
            bulk_ld(stb + 8192, mSrc + ((atile0 + c) << 11), 2048, MB + c * 8);
            bulk_ld(stb + 10240, bsrc + ((size_t)c << 14), 16384, MB + c * 8);
        }
    }

    for (int kc = 0; kc < NKC; ++kc) {
        int st = kc & 3;
        uint32_t parity = (uint32_t)((kc >> 2) & 1);
        mbar_wait(MB + st * 8, parity);
        __syncthreads();

        if (tid == 0 && kc + 3 < NKC) {
            int s2 = (kc + 3) & 3;
            uint32_t stb = ST + s2 * STAGE_SZ;
            mbar_expect_tx(MB + s2 * 8, STAGE_SZ);
            bulk_ld(stb, aSrc + ((atile0 + kc + 3) << 13), 8192, MB + s2 * 8);
            bulk_ld(stb + 8192, mSrc + ((atile0 + kc + 3) << 11), 2048, MB + s2 * 8);
            bulk_ld(stb + 10240, bsrc + ((size_t)(kc + 3) << 14), 16384, MB + s2 * 8);
        }

        const uint32_t AHc = ST + st * STAGE_SZ;
        const uint32_t MEc = AHc + 8192;
        const uint32_t BHc = AHc + 10240;

        // metadata: 8 conflict-free scalar loads, zero merge ALU. mr[mi*2+q].
        uint32_t mr[8];
#pragma unroll
        for (int w = 0; w < 8; ++w)
            asm volatile("ld.shared.b32 %0, [%1];"
                         : "=r"(mr[w]) : "r"(MEc + me_base + w * 128));

#pragma unroll
        for (int q = 0; q < 2; ++q) {
            uint32_t asp[4][4], bsp[4][4];
#pragma unroll
            for (int mi = 0; mi < 4; ++mi)
                ldsm4(AHc + swa[mi][q],
                      asp[mi][0], asp[mi][1], asp[mi][2], asp[mi][3]);
#pragma unroll
            for (int ni = 0; ni < 2; ++ni) {
                uint32_t r0, r1, r2, r3;
                ldsm4(BHc + swb[ni][2 * q], r0, r1, r2, r3);
                bsp[2 * ni][0] = r0; bsp[2 * ni][1] = r1;
                bsp[2 * ni + 1][0] = r2; bsp[2 * ni + 1][1] = r3;
                ldsm4(BHc + swb[ni][2 * q + 1], r0, r1, r2, r3);
                bsp[2 * ni][2] = r0; bsp[2 * ni][3] = r1;
                bsp[2 * ni + 1][2] = r2; bsp[2 * ni + 1][3] = r3;
            }
#pragma unroll
            for (int mi = 0; mi < 4; ++mi)
#pragma unroll
                for (int nj = 0; nj < 4; ++nj)
                    mmasp(acc[mi][nj], asp[mi], bsp[nj], mr[mi * 2 + q]);
        }
    }

    // epilogue (optional fused sigmoid for the z instance)
#pragma unroll
    for (int mi = 0; mi < 4; ++mi) {
#pragma unroll
        for (int nj = 0; nj < 4; ++nj) {
            float v0 = acc[mi][nj][0], v1 = acc[mi][nj][1];
            float v2 = acc[mi][nj][2], v3 = acc[mi][nj][3];
            if (dosig) {
                v0 = 1.0f / (1.0f + __expf(-v0));
                v1 = 1.0f / (1.0f + __expf(-v1));
                v2 = 1.0f / (1.0f + __expf(-v2));
                v3 = 1.0f / (1.0f + __expf(-v3));
            }
            int row = mt * 128 + wm * 64 + mi * 16 + (lane >> 2);
            int col = nb * 128 + wn * 32 + nj * 8 + 2 * (lane & 3);
            *(float2*)&out[(size_t)row * DD + col] = make_float2(v0, v1);
            *(float2*)&out[(size_t)(row + 8) * DD + col] = make_float2(v2, v3);
        }
    }
}

// ---------------------------------------------------------------------------
// Segmented scan, SEG=64 (z already sigmoided). p1/p2 vectorized float4.
// ---------------------------------------------------------------------------
__global__ __launch_bounds__(256) void scan_p1(
    const float4* __restrict__ z4, const float4* __restrict__ hb4) {
    int gid = blockIdx.x * blockDim.x + threadIdx.x;
    if (gid >= BD * SEG * (DD / 4)) return;
    int d4 = gid & 127;
    int bs = gid >> 7;
    int seg = bs & (SEG - 1);
    int b = bs / SEG;
    size_t base = ((size_t)b * TD * DD + (size_t)seg * SEGLEN * DD) / 4 + d4;
    float4 A = make_float4(1.f, 1.f, 1.f, 1.f);
    float4 Bv = make_float4(0.f, 0.f, 0.f, 0.f);
#pragma unroll 4
    for (int t = 0; t < SEGLEN; ++t) {
        size_t idx = base + (size_t)t * (DD / 4);
        float4 zv = z4[idx];
        float4 hv = hb4[idx];
        float ax = 1.f - zv.x, ay = 1.f - zv.y, az = 1.f - zv.z, aw = 1.f - zv.w;
        A.x *= ax; A.y *= ay; A.z *= az; A.w *= aw;
        Bv.x = fmaf(ax, Bv.x, zv.x * hv.x);
        Bv.y = fmaf(ay, Bv.y, zv.y * hv.y);
        Bv.z = fmaf(az, Bv.z, zv.z * hv.z);
        Bv.w = fmaf(aw, Bv.w, zv.w * hv.w);
    }
    ((float4*)g_scanA)[gid] = A;
    ((float4*)g_scanB)[gid] = Bv;
}

__global__ __launch_bounds__(256) void scan_p2() {
    int c = blockIdx.x * blockDim.x + threadIdx.x;
    if (c >= BD * (DD / 4)) return;
    int d4 = c & 127;
    int b = c >> 7;
    float4 h = make_float4(0.f, 0.f, 0.f, 0.f);
#pragma unroll
    for (int seg = 0; seg < SEG; ++seg) {
        int gid = (b * SEG + seg) * 128 + d4;
        ((float4*)g_scanH)[gid] = h;
        float4 A = ((float4*)g_scanA)[gid];
        float4 Bv = ((float4*)g_scanB)[gid];
        h.x = fmaf(A.x, h.x, Bv.x);
        h.y = fmaf(A.y, h.y, Bv.y);
        h.z = fmaf(A.z, h.z, Bv.z);
        h.w = fmaf(A.w, h.w, Bv.w);
    }
}

// p3 + maxabs norm + FUSED next-layer compressed-A build (nsets param sets).
// block = 512 threads = all d of one (b, seg).
__global__ __launch_bounds__(512) void scan_p3_norm_fuse(
    const float* __restrict__ z, const float* __restrict__ hb,
    float* __restrict__ h, const float* __restrict__ P0,
    const float* __restrict__ P1, int nsets) {
    __shared__ float red[34];
    int blk = blockIdx.x;
    int d = threadIdx.x;
    int seg = blk & (SEG - 1);
    int b = blk / SEG;
    int lane = d & 31, wid = d >> 5;
    size_t base = (size_t)b * TD * DD + (size_t)seg * SEGLEN * DD + d;
    float hc = g_scanH[(blk << 9) + d];

    float p0[8], p1[8];
#pragma unroll
    for (int j = 0; j < 8; ++j) p0[j] = __ldg(&P0[d * 8 + j]);
    if (nsets > 1) {
#pragma unroll
        for (int j = 0; j < 8; ++j) p1[j] = __ldg(&P1[d * 8 + j]);
    }
    const int il = d & 7;
    const int kc = d >> 3;
    const int n0g = b * TD + seg * SEGLEN;
    const int mt = n0g >> 7;
    const int nnb = n0g & 127;
    char* Ab0 = (char*)g_A[0] + ((size_t)(mt * NKC + kc) << 13);
    uint8_t* Mb0 = g_MM[0] + ((size_t)(mt * NKC + kc) << 11);
    char* Ab1 = (char*)g_A[1] + ((size_t)(mt * NKC + kc) << 13);
    uint8_t* Mb1 = g_MM[1] + ((size_t)(mt * NKC + kc) << 11);
    const uint32_t ilo = (uint32_t)((il >> 2) * 32 + (il & 3) * 8);

    for (int t = 0; t < SEGLEN; ++t) {
        size_t idx = base + (size_t)t * DD;
        float zv = z[idx];
        hc = fmaf(zv, hb[idx] - hc, hc);
        int slot = (t & 1) * 17;
        float m = fabsf(hc);
#pragma unroll
        for (int o = 16; o; o >>= 1)
            m = fmaxf(m, __shfl_xor_sync(0xffffffffu, m, o));
        if (lane == 0) red[slot + wid] = m;
        __syncthreads();
        if (wid == 0) {
            float mm = red[slot + (lane & 15)];
#pragma unroll
            for (int o = 8; o; o >>= 1)
                mm = fmaxf(mm, __shfl_xor_sync(0xffffffffu, mm, o));
            if (lane == 0) red[slot + 16] = mm;
        }
        __syncthreads();
        float inv = 1.0f / (red[slot + 16] + 1e-6f);
        float hn = hc * inv;
        h[idx] = hn;

        int nn = nnb + t;
        uint32_t aoff = SWZ((uint32_t)((nn >> 1) * 128 + (nn & 1) * 64) + ilo);
        uint32_t w0, w1, mb;
        hat_compress(hn, p0, w0, w1, mb);
        *(uint2*)(Ab0 + aoff) = make_uint2(w0, w1);
        Mb0[meta_off(nn, il, 0)] = (uint8_t)mb;
        Mb0[meta_off(nn, il, 1)] = (uint8_t)mb;
        if (nsets > 1) {
            hat_compress(hn, p1, w0, w1, mb);
            *(uint2*)(Ab1 + aoff) = make_uint2(w0, w1);
            Mb1[meta_off(nn, il, 0)] = (uint8_t)mb;
            Mb1[meta_off(nn, il, 1)] = (uint8_t)mb;
        }
    }
}

// ---------------------------------------------------------------------------
// kernel_launch (launch #4 = paired apl_hmma for the ncu capture window)
// ---------------------------------------------------------------------------
extern "C" void kernel_launch(void* const* d_in, const int* in_sizes, int n_in,
                              void* d_out, int out_size) {
    const float* x   = (const float*)d_in[0];
    const float* pz0 = (const float*)d_in[1];
    const float* vz0 = (const float*)d_in[2];
    const float* ph0 = (const float*)d_in[3];
    const float* vh0 = (const float*)d_in[4];
    const float* pz1 = (const float*)d_in[5];
    const float* vz1 = (const float*)d_in[6];
    const float* ph1 = (const float*)d_in[7];
    const float* vh1 = (const float*)d_in[8];
    const float* po  = (const float*)d_in[9];
    const float* vo  = (const float*)d_in[10];

    const int N = in_sizes[0] / DD;  // 16384

    float *zb, *hb;
    __half *bhi, *a0, *a1;
    uint8_t *m0, *m1;
    cudaGetSymbolAddress((void**)&zb, g_z);
    cudaGetSymbolAddress((void**)&hb, g_hbar);
    cudaGetSymbolAddress((void**)&bhi, g_bt_hi);
    cudaGetSymbolAddress((void**)&a0, g_A);
    cudaGetSymbolAddress((void**)&m0, g_MM);
    a1 = a0 + (size_t)NMT * NKC * 4096;
    m1 = m0 + (size_t)NMT * NKC * 2048;

    static int smem_set = 0;
    if (!smem_set) {
        cudaFuncSetAttribute(apl_hmma_kernel,
                             cudaFuncAttributeMaxDynamicSharedMemorySize, SMEM_REQ);
        smem_set = 1;
    }

    float* out = (float*)d_out;
    float* h1  = out + (size_t)N * DD;
    float* h2  = h1 + (size_t)N * DD;

    dim3 sp3(64, 4, 3);
    dim3 sp2(64, 4, 2);
    dim3 agrid2(NMT, NKC, 2);
    dim3 gpair(NMT, 4, 2);
    dim3 gone(NMT, 4, 1);
    const int p1_blocks = (BD * SEG * (DD / 4) + 255) / 256;
    const int p2_blocks = (BD * (DD / 4) + 255) / 256;
    const int p3_blocks = BD * SEG;
    const size_t LSZ = (size_t)4 * 64 * 8192;

    // [1][2] pre-stage all V into chunked/pre-swizzled fp16 B tiles
    split_chunk_kernel<<<sp3, 256>>>(vz0, vh0, vz1, 0);
    split_chunk_kernel<<<sp2, 256>>>(vh1, vo, vo, 3);

    // ---- layer 0 ----
    build_A_kernel<<<agrid2, 256>>>(x, pz0, ph0);                            // [3]
    apl_hmma_kernel<<<gpair, 256, SMEM_REQ>>>(a0, m0, a1, m1,
                                              bhi + 0 * LSZ, bhi + 1 * LSZ,
                                              zb, hb, 1);                    // [4] profiled
    scan_p1<<<p1_blocks, 256>>>((const float4*)zb, (const float4*)hb);
    scan_p2<<<p2_blocks, 256>>>();
    scan_p3_norm_fuse<<<p3_blocks, 512>>>(zb, hb, h1, pz1, ph1, 2);

    // ---- layer 1 (A tiles built by fused p3) ----
    apl_hmma_kernel<<<gpair, 256, SMEM_REQ>>>(a0, m0, a1, m1,
                                              bhi + 2 * LSZ, bhi + 3 * LSZ,
                                              zb, hb, 1);
    scan_p1<<<p1_blocks, 256>>>((const float4*)zb, (const float4*)hb);
    scan_p2<<<p2_blocks, 256>>>();
    scan_p3_norm_fuse<<<p3_blocks, 512>>>(zb, hb, h2, po, po, 1);

    // ---- output APL (A tiles built by fused p3) ----
    apl_hmma_kernel<<<gone, 256, SMEM_REQ>>>(a0, m0, a0, m0,
                                             bhi + 4 * LSZ, bhi + 4 * LSZ,
                                             out, out, 0);
}

// round 16
// speedup vs baseline: 1.1263x; 1.0544x over previous
#include <cuda_runtime.h>
#include <cuda_fp16.h>
#include <math.h>
#include <stdint.h>

// Problem constants
#define BD   8
#define TD   2048
#define DD   512
#define NTOT (BD * TD)     // 16384
#define KTOT 4096          // D * P
#define NKC  64            // K-chunks of 64 elements
#define NMT  128           // M-tiles of 128 rows
#define SEG  64
#define SEGLEN (TD / SEG)  // 32

// ---------------------------------------------------------------------------
// Scratch (device globals — no allocations allowed)
// ---------------------------------------------------------------------------
__device__ float g_z[(size_t)NTOT * DD];    // sigmoid(z logits)
__device__ float g_hbar[(size_t)NTOT * DD];
// Pre-swizzled B chunk tiles: [layer][nb(4)][kc(64)] 16KB each
__device__ __align__(128) __half g_bt_hi[5][(size_t)4 * 64 * 8192];
// Compressed 2:4 A tiles: [inst(2)][mt(128)][kc(64)] 8KB each
__device__ __align__(128) __half   g_A[2][(size_t)NMT * NKC * 4096];
// Metadata 1KB per (mt,kc): word w=(r*2+b)+16*(wm*8+mi*2+q), bytes 2s+c
__device__ __align__(128) uint8_t g_MM[2][(size_t)NMT * NKC * 1024];
// scan scratch
__device__ float g_scanA[BD * SEG * DD];
__device__ float g_scanB[BD * SEG * DD];
__device__ float g_scanH[BD * SEG * DD];

// ---------------------------------------------------------------------------
// helpers
// ---------------------------------------------------------------------------
__device__ __forceinline__ uint32_t smem_u32(const void* p) {
    uint32_t a;
    asm("{ .reg .u64 t; cvta.to.shared.u64 t, %1; cvt.u32.u64 %0, t; }"
        : "=r"(a) : "l"(p));
    return a;
}

#define SWZ(x) ((x) ^ (((x) >> 3) & 0x70))

__device__ __forceinline__ void mbar_init(uint32_t a, uint32_t cnt) {
    asm volatile("mbarrier.init.shared.b64 [%0], %1;" :: "r"(a), "r"(cnt) : "memory");
}

__device__ __forceinline__ void mbar_wait(uint32_t a, uint32_t ph) {
    asm volatile(
        "{\n\t.reg .pred P;\n\t"
        "W%=:\n\t"
        "mbarrier.try_wait.parity.acquire.cta.shared::cta.b64 P, [%0], %1, 0x989680;\n\t"
        "@P bra.uni D%=;\n\t"
        "bra.uni W%=;\n\t"
        "D%=:\n\t}"
        :: "r"(a), "r"(ph) : "memory");
}

__device__ __forceinline__ void mbar_expect_tx(uint32_t a, uint32_t bytes) {
    asm volatile("mbarrier.arrive.expect_tx.shared.b64 _, [%0], %1;"
                 :: "r"(a), "r"(bytes) : "memory");
}

__device__ __forceinline__ void bulk_ld(uint32_t dst, const void* src,
                                        uint32_t bytes, uint32_t mbar) {
    asm volatile(
        "cp.async.bulk.shared::cluster.global.mbarrier::complete_tx::bytes "
        "[%0], [%1], %2, [%3];"
        :: "r"(dst), "l"(src), "r"(bytes), "r"(mbar) : "memory");
}

// 2:4 compression of the hat pair (1-t @ k, t @ k+1) within an 8-wide i-block.
__device__ __forceinline__ void hat_compress(float x, const float* p,
                                             uint32_t& w0, uint32_t& w1,
                                             uint32_t& mb) {
    int k = 0;
    float pl = p[0], pr = p[1];
#pragma unroll
    for (int j = 1; j <= 6; ++j)
        if (p[j] < x) { k = j; pl = p[j]; pr = p[j + 1]; }
    float t = fminf(fmaxf((x - pl) / (pr - pl), 0.0f), 1.0f);
    __half2 h2 = __floats2half2_rn(1.0f - t, t);
    uint32_t P = *(uint32_t*)&h2;
    uint32_t m0, m1;
    if (k <= 2)      { w0 = P;       w1 = 0u;      m0 = (uint32_t)(k | ((k + 1) << 2)); m1 = 4u; }
    else if (k == 3) { w0 = P << 16; w1 = P >> 16; m0 = 12u;                            m1 = 4u; }
    else             { int kp = k - 4; w0 = 0u; w1 = P; m0 = 4u;
                       m1 = (uint32_t)(kp | ((kp + 1) << 2)); }
    mb = m0 | (m1 << 4);
}

// Meta byte offset inside 1KB tile: w=(r*2+b)+16*(u*8+v*2+a), byte = 2s+c
__device__ __forceinline__ uint32_t meta_off(int n, int il) {
    int u = n >> 6, v = (n >> 4) & 3, s = (n >> 3) & 1, r = n & 7;
    int a = il >> 2, b = (il >> 1) & 1, c = il & 1;
    int w = (r * 2 + b) + 16 * (u * 8 + v * 2 + a);
    return (uint32_t)(w * 4 + 2 * s + c);
}

// ---------------------------------------------------------------------------
// split_chunk: v (4096 x 512 f32) -> pre-swizzled 16KB B chunk tiles, fp16.
// ---------------------------------------------------------------------------
__global__ __launch_bounds__(256) void split_chunk_kernel(
    const float* __restrict__ va, const float* __restrict__ vb,
    const float* __restrict__ vc, int ibase) {
    int kc = blockIdx.x, nb = blockIdx.y, z = blockIdx.z;
    const float* v = (z == 0) ? va : (z == 1) ? vb : vc;
    int layer = ibase + z;
    size_t tile_off = ((size_t)layer * 256 + nb * 64 + kc) << 14;  // bytes
    char* hib = (char*)g_bt_hi + tile_off;

    int r = threadIdx.x & 127;
    int chalf = threadIdx.x >> 7;
#pragma unroll
    for (int j = 0; j < 32; ++j) {
        int c = chalf * 32 + j;
        float val = v[(size_t)(kc * 64 + c) * DD + nb * 128 + r];
        uint32_t off = SWZ((uint32_t)(r * 128 + c * 2));
        *(__half*)(hib + off) = __float2half_rn(val);
    }
}

// ---------------------------------------------------------------------------
// build_A_kernel (layer 0): one thread per metadata word (4 hats),
// coalesced u32 meta store.
// ---------------------------------------------------------------------------
__global__ __launch_bounds__(256) void build_A_kernel(
    const float* __restrict__ X, const float* __restrict__ P0,
    const float* __restrict__ P1) {
    int mt = blockIdx.x, kc = blockIdx.y, z = blockIdx.z;
    const float* Pp = z ? P1 : P0;
    char* Ab = (char*)g_A[z] + ((size_t)(mt * NKC + kc) << 13);
    uint8_t* Mb = g_MM[z] + ((size_t)(mt * NKC + kc) << 10);
    int w = threadIdx.x;              // word index 0..255
    int rp = w & 15;
    int r = rp >> 1, b = rp & 1;
    int rest = w >> 4;
    int u = rest >> 3, v = (rest >> 1) & 3, a = rest & 1;
    int il0 = a * 4 + b * 2;
    int n0 = u * 64 + v * 16 + r;
    int bm = mt * 128;

    float p[2][8];
#pragma unroll
    for (int c = 0; c < 2; ++c) {
        int i = kc * 8 + il0 + c;
#pragma unroll
        for (int j = 0; j < 8; ++j) p[c][j] = __ldg(&Pp[i * 8 + j]);
    }

    uint32_t word = 0;
#pragma unroll
    for (int s = 0; s < 2; ++s) {
        int n = n0 + 8 * s;
#pragma unroll
        for (int c = 0; c < 2; ++c) {
            int il = il0 + c;
            float x = __ldg(&X[(size_t)(bm + n) * DD + kc * 8 + il]);
            uint32_t w0, w1, mb;
            hat_compress(x, p[c], w0, w1, mb);
            uint32_t off = (uint32_t)((n >> 1) * 128 + (n & 1) * 64 +
                                      (il >> 2) * 32 + (il & 3) * 8);
            *(uint2*)(Ab + SWZ(off)) = make_uint2(w0, w1);
            word |= mb << ((2 * s + c) * 8);
        }
    }
    *(uint32_t*)(Mb + w * 4) = word;
}

// ---------------------------------------------------------------------------
// APL sparse-HMMA GEMM. 4-stage bulk-DMA ring of [A 8K][meta 1K][B 16K].
// 256 threads, 8 warps (2Mx4N), warp tile 64x32, CTA 128x128, 2 CTA/SM.
// ---------------------------------------------------------------------------
#define STAGE_SZ 25600
#define SMEM_REQ (1024 + 1024 + 4 * STAGE_SZ)

__device__ __forceinline__ void ldsm4(uint32_t a, uint32_t& r0, uint32_t& r1,
                                      uint32_t& r2, uint32_t& r3) {
    asm volatile("ldmatrix.sync.aligned.m8n8.x4.shared.b16 {%0,%1,%2,%3}, [%4];"
                 : "=r"(r0), "=r"(r1), "=r"(r2), "=r"(r3) : "r"(a));
}

__device__ __forceinline__ void mmasp(float* d, const uint32_t* a,
                                      const uint32_t* b, uint32_t e) {
    asm volatile(
        "mma.sp::ordered_metadata.sync.aligned.m16n8k32.row.col.f32.f16.f16.f32 "
        "{%0,%1,%2,%3}, {%4,%5,%6,%7}, {%8,%9,%10,%11}, {%0,%1,%2,%3}, %12, 0x0;"
        : "+f"(d[0]), "+f"(d[1]), "+f"(d[2]), "+f"(d[3])
        : "r"(a[0]), "r"(a[1]), "r"(a[2]), "r"(a[3]),
          "r"(b[0]), "r"(b[1]), "r"(b[2]), "r"(b[3]), "r"(e));
}

__global__ void __launch_bounds__(256, 2) apl_hmma_kernel(
    const __half* __restrict__ A0, const uint8_t* __restrict__ M0,
    const __half* __restrict__ A1, const uint8_t* __restrict__ M1,
    const __half* __restrict__ B0, const __half* __restrict__ B1,
    float* __restrict__ out0, float* __restrict__ out1, int sigz) {
    const int zz = blockIdx.z;
    const char* aSrc = (const char*)(zz ? A1 : A0);
    const char* mSrc = (const char*)(zz ? M1 : M0);
    const __half* Bhi = zz ? B1 : B0;
    float* out = zz ? out1 : out0;
    const int dosig = sigz && (zz == 0);

    extern __shared__ char smem[];
    uint32_t sb = (smem_u32(smem) + 1023u) & ~1023u;
    const uint32_t MB = sb;
    const uint32_t ST = sb + 1024;
    const int tid = threadIdx.x;
    const int lane = tid & 31;
    const int wid = tid >> 5;
    const int wm = wid & 1;
    const int wn = wid >> 1;
    const int mt = blockIdx.x;
    const int nb = blockIdx.y;

    const char* bsrc = (const char*)Bhi + ((size_t)nb * 64 << 14);
    const size_t atile0 = (size_t)mt * NKC;

    if (tid == 0) {
        mbar_init(MB + 0, 1);
        mbar_init(MB + 8, 1);
        mbar_init(MB + 16, 1);
        mbar_init(MB + 24, 1);
        asm volatile("fence.proxy.async.shared::cta;" ::: "memory");
    }
    __syncthreads();

    float acc[4][4][4];
#pragma unroll
    for (int mi = 0; mi < 4; ++mi)
#pragma unroll
        for (int nj = 0; nj < 4; ++nj)
#pragma unroll
            for (int u = 0; u < 4; ++u) acc[mi][nj][u] = 0.0f;

    // hoisted, fully swizzled per-thread offsets (loop-invariant)
    uint32_t swa[4][2], swb[2][4];
#pragma unroll
    for (int mi = 0; mi < 4; ++mi) {
        int arow = wm * 64 + mi * 16 + (lane & 15);
        uint32_t base = (uint32_t)((arow >> 1) * 128 + (arow & 1) * 64 +
                                   (lane >> 4) * 16);
#pragma unroll
        for (int q = 0; q < 2; ++q) swa[mi][q] = SWZ(base + q * 32);
    }
#pragma unroll
    for (int ni = 0; ni < 2; ++ni) {
        int row = wn * 32 + ni * 16 + (lane & 7) + ((lane & 16) >> 1);
        uint32_t base = (uint32_t)(row * 128 + ((lane >> 3) & 1) * 16);
#pragma unroll
        for (int k4 = 0; k4 < 4; ++k4) swb[ni][k4] = SWZ(base + k4 * 32);
    }
    // meta base: ((lane>>2)*2 + (lane&1))*4 + wm*512; word (mi,q) at +(mi*2+q)*64
    const uint32_t me_base = (uint32_t)((((lane >> 2) * 2 + (lane & 1)) * 4) +
                                        wm * 512);

    if (tid == 0) {
#pragma unroll
        for (int c = 0; c < 3; ++c) {
            uint32_t stb = ST + c * STAGE_SZ;
            mbar_expect_tx(MB + c * 8, STAGE_SZ);
            bulk_ld(stb, aSrc + ((atile0 + c) << 13), 8192, MB + c * 8);
            bulk_ld(stb + 8192, mSrc + ((atile0 + c) << 10), 1024, MB + c * 8);
            bulk_ld(stb + 9216, bsrc + ((size_t)c << 14), 16384, MB + c * 8);
        }
    }

    for (int kc = 0; kc < NKC; ++kc) {
        int st = kc & 3;
        uint32_t parity = (uint32_t)((kc >> 2) & 1);
        mbar_wait(MB + st * 8, parity);
        __syncthreads();

        if (tid == 0 && kc + 3 < NKC) {
            int s2 = (kc + 3) & 3;
            uint32_t stb = ST + s2 * STAGE_SZ;
            mbar_expect_tx(MB + s2 * 8, STAGE_SZ);
            bulk_ld(stb, aSrc + ((atile0 + kc + 3) << 13), 8192, MB + s2 * 8);
            bulk_ld(stb + 8192, mSrc + ((atile0 + kc + 3) << 10), 1024, MB + s2 * 8);
            bulk_ld(stb + 9216, bsrc + ((size_t)(kc + 3) << 14), 16384, MB + s2 * 8);
        }

        const uint32_t AHc = ST + st * STAGE_SZ;
        const uint32_t MEc = AHc + 8192;
        const uint32_t BHc = AHc + 9216;

        // metadata: 8 scalar loads, broadcast pairs, zero merge ALU. mr[mi*2+q].
        uint32_t mr[8];
#pragma unroll
        for (int w = 0; w < 8; ++w)
            asm volatile("ld.shared.b32 %0, [%1];"
                         : "=r"(mr[w]) : "r"(MEc + me_base + w * 64));

#pragma unroll
        for (int q = 0; q < 2; ++q) {
            uint32_t asp[4][4], bsp[4][4];
#pragma unroll
            for (int mi = 0; mi < 4; ++mi)
                ldsm4(AHc + swa[mi][q],
                      asp[mi][0], asp[mi][1], asp[mi][2], asp[mi][3]);
#pragma unroll
            for (int ni = 0; ni < 2; ++ni) {
                uint32_t r0, r1, r2, r3;
                ldsm4(BHc + swb[ni][2 * q], r0, r1, r2, r3);
                bsp[2 * ni][0] = r0; bsp[2 * ni][1] = r1;
                bsp[2 * ni + 1][0] = r2; bsp[2 * ni + 1][1] = r3;
                ldsm4(BHc + swb[ni][2 * q + 1], r0, r1, r2, r3);
                bsp[2 * ni][2] = r0; bsp[2 * ni][3] = r1;
                bsp[2 * ni + 1][2] = r2; bsp[2 * ni + 1][3] = r3;
            }
#pragma unroll
            for (int mi = 0; mi < 4; ++mi)
#pragma unroll
                for (int nj = 0; nj < 4; ++nj)
                    mmasp(acc[mi][nj], asp[mi], bsp[nj], mr[mi * 2 + q]);
        }
    }

    // epilogue (optional fused sigmoid for the z instance)
#pragma unroll
    for (int mi = 0; mi < 4; ++mi) {
#pragma unroll
        for (int nj = 0; nj < 4; ++nj) {
            float v0 = acc[mi][nj][0], v1 = acc[mi][nj][1];
            float v2 = acc[mi][nj][2], v3 = acc[mi][nj][3];
            if (dosig) {
                v0 = 1.0f / (1.0f + __expf(-v0));
                v1 = 1.0f / (1.0f + __expf(-v1));
                v2 = 1.0f / (1.0f + __expf(-v2));
                v3 = 1.0f / (1.0f + __expf(-v3));
            }
            int row = mt * 128 + wm * 64 + mi * 16 + (lane >> 2);
            int col = nb * 128 + wn * 32 + nj * 8 + 2 * (lane & 3);
            *(float2*)&out[(size_t)row * DD + col] = make_float2(v0, v1);
            *(float2*)&out[(size_t)(row + 8) * DD + col] = make_float2(v2, v3);
        }
    }
}

// ---------------------------------------------------------------------------
// Segmented scan, SEG=64 (z already sigmoided). p1/p2 vectorized float4.
// ---------------------------------------------------------------------------
__global__ __launch_bounds__(256) void scan_p1(
    const float4* __restrict__ z4, const float4* __restrict__ hb4) {
    int gid = blockIdx.x * blockDim.x + threadIdx.x;
    if (gid >= BD * SEG * (DD / 4)) return;
    int d4 = gid & 127;
    int bs = gid >> 7;
    int seg = bs & (SEG - 1);
    int b = bs / SEG;
    size_t base = ((size_t)b * TD * DD + (size_t)seg * SEGLEN * DD) / 4 + d4;
    float4 A = make_float4(1.f, 1.f, 1.f, 1.f);
    float4 Bv = make_float4(0.f, 0.f, 0.f, 0.f);
#pragma unroll 4
    for (int t = 0; t < SEGLEN; ++t) {
        size_t idx = base + (size_t)t * (DD / 4);
        float4 zv = z4[idx];
        float4 hv = hb4[idx];
        float ax = 1.f - zv.x, ay = 1.f - zv.y, az = 1.f - zv.z, aw = 1.f - zv.w;
        A.x *= ax; A.y *= ay; A.z *= az; A.w *= aw;
        Bv.x = fmaf(ax, Bv.x, zv.x * hv.x);
        Bv.y = fmaf(ay, Bv.y, zv.y * hv.y);
        Bv.z = fmaf(az, Bv.z, zv.z * hv.z);
        Bv.w = fmaf(aw, Bv.w, zv.w * hv.w);
    }
    ((float4*)g_scanA)[gid] = A;
    ((float4*)g_scanB)[gid] = Bv;
}

__global__ __launch_bounds__(256) void scan_p2() {
    int c = blockIdx.x * blockDim.x + threadIdx.x;
    if (c >= BD * (DD / 4)) return;
    int d4 = c & 127;
    int b = c >> 7;
    float4 h = make_float4(0.f, 0.f, 0.f, 0.f);
#pragma unroll
    for (int seg = 0; seg < SEG; ++seg) {
        int gid = (b * SEG + seg) * 128 + d4;
        ((float4*)g_scanH)[gid] = h;
        float4 A = ((float4*)g_scanA)[gid];
        float4 Bv = ((float4*)g_scanB)[gid];
        h.x = fmaf(A.x, h.x, Bv.x);
        h.y = fmaf(A.y, h.y, Bv.y);
        h.z = fmaf(A.z, h.z, Bv.z);
        h.w = fmaf(A.w, h.w, Bv.w);
    }
}

// p3 + maxabs norm + FUSED next-layer compressed-A build (nsets param sets).
// block = 512 threads = all d of one (b, seg).
__global__ __launch_bounds__(512) void scan_p3_norm_fuse(
    const float* __restrict__ z, const float* __restrict__ hb,
    float* __restrict__ h, const float* __restrict__ P0,
    const float* __restrict__ P1, int nsets) {
    __shared__ float red[34];
    int blk = blockIdx.x;
    int d = threadIdx.x;
    int seg = blk & (SEG - 1);
    int b = blk / SEG;
    int lane = d & 31, wid = d >> 5;
    size_t base = (size_t)b * TD * DD + (size_t)seg * SEGLEN * DD + d;
    float hc = g_scanH[(blk << 9) + d];

    float p0[8], p1[8];
#pragma unroll
    for (int j = 0; j < 8; ++j) p0[j] = __ldg(&P0[d * 8 + j]);
    if (nsets > 1) {
#pragma unroll
        for (int j = 0; j < 8; ++j) p1[j] = __ldg(&P1[d * 8 + j]);
    }
    const int il = d & 7;
    const int kc = d >> 3;
    const int n0g = b * TD + seg * SEGLEN;
    const int mt = n0g >> 7;
    const int nnb = n0g & 127;
    char* Ab0 = (char*)g_A[0] + ((size_t)(mt * NKC + kc) << 13);
    uint8_t* Mb0 = g_MM[0] + ((size_t)(mt * NKC + kc) << 10);
    char* Ab1 = (char*)g_A[1] + ((size_t)(mt * NKC + kc) << 13);
    uint8_t* Mb1 = g_MM[1] + ((size_t)(mt * NKC + kc) << 10);
    const uint32_t ilo = (uint32_t)((il >> 2) * 32 + (il & 3) * 8);

    for (int t = 0; t < SEGLEN; ++t) {
        size_t idx = base + (size_t)t * DD;
        float zv = z[idx];
        hc = fmaf(zv, hb[idx] - hc, hc);
        int slot = (t & 1) * 17;
        float m = fabsf(hc);
#pragma unroll
        for (int o = 16; o; o >>= 1)
            m = fmaxf(m, __shfl_xor_sync(0xffffffffu, m, o));
        if (lane == 0) red[slot + wid] = m;
        __syncthreads();
        if (wid == 0) {
            float mm = red[slot + (lane & 15)];
#pragma unroll
            for (int o = 8; o; o >>= 1)
                mm = fmaxf(mm, __shfl_xor_sync(0xffffffffu, mm, o));
            if (lane == 0) red[slot + 16] = mm;
        }
        __syncthreads();
        float inv = 1.0f / (red[slot + 16] + 1e-6f);
        float hn = hc * inv;
        h[idx] = hn;

        int nn = nnb + t;
        uint32_t aoff = SWZ((uint32_t)((nn >> 1) * 128 + (nn & 1) * 64) + ilo);
        uint32_t moff = meta_off(nn, il);
        uint32_t w0, w1, mb;
        hat_compress(hn, p0, w0, w1, mb);
        *(uint2*)(Ab0 + aoff) = make_uint2(w0, w1);
        Mb0[moff] = (uint8_t)mb;
        if (nsets > 1) {
            hat_compress(hn, p1, w0, w1, mb);
            *(uint2*)(Ab1 + aoff) = make_uint2(w0, w1);
            Mb1[moff] = (uint8_t)mb;
        }
    }
}

// ---------------------------------------------------------------------------
// kernel_launch (launch #4 = paired apl_hmma for the ncu capture window)
// ---------------------------------------------------------------------------
extern "C" void kernel_launch(void* const* d_in, const int* in_sizes, int n_in,
                              void* d_out, int out_size) {
    const float* x   = (const float*)d_in[0];
    const float* pz0 = (const float*)d_in[1];
    const float* vz0 = (const float*)d_in[2];
    const float* ph0 = (const float*)d_in[3];
    const float* vh0 = (const float*)d_in[4];
    const float* pz1 = (const float*)d_in[5];
    const float* vz1 = (const float*)d_in[6];
    const float* ph1 = (const float*)d_in[7];
    const float* vh1 = (const float*)d_in[8];
    const float* po  = (const float*)d_in[9];
    const float* vo  = (const float*)d_in[10];

    const int N = in_sizes[0] / DD;  // 16384

    float *zb, *hb;
    __half *bhi, *a0, *a1;
    uint8_t *m0, *m1;
    cudaGetSymbolAddress((void**)&zb, g_z);
    cudaGetSymbolAddress((void**)&hb, g_hbar);
    cudaGetSymbolAddress((void**)&bhi, g_bt_hi);
    cudaGetSymbolAddress((void**)&a0, g_A);
    cudaGetSymbolAddress((void**)&m0, g_MM);
    a1 = a0 + (size_t)NMT * NKC * 4096;
    m1 = m0 + (size_t)NMT * NKC * 1024;

    static int smem_set = 0;
    if (!smem_set) {
        cudaFuncSetAttribute(apl_hmma_kernel,
                             cudaFuncAttributeMaxDynamicSharedMemorySize, SMEM_REQ);
        smem_set = 1;
    }

    float* out = (float*)d_out;
    float* h1  = out + (size_t)N * DD;
    float* h2  = h1 + (size_t)N * DD;

    dim3 sp3(64, 4, 3);
    dim3 sp2(64, 4, 2);
    dim3 agrid2(NMT, NKC, 2);
    dim3 gpair(NMT, 4, 2);
    dim3 gone(NMT, 4, 1);
    const int p1_blocks = (BD * SEG * (DD / 4) + 255) / 256;
    const int p2_blocks = (BD * (DD / 4) + 255) / 256;
    const int p3_blocks = BD * SEG;
    const size_t LSZ = (size_t)4 * 64 * 8192;

    // [1][2] pre-stage all V into chunked/pre-swizzled fp16 B tiles
    split_chunk_kernel<<<sp3, 256>>>(vz0, vh0, vz1, 0);
    split_chunk_kernel<<<sp2, 256>>>(vh1, vo, vo, 3);

    // ---- layer 0 ----
    build_A_kernel<<<agrid2, 256>>>(x, pz0, ph0);                            // [3]
    apl_hmma_kernel<<<gpair, 256, SMEM_REQ>>>(a0, m0, a1, m1,
                                              bhi + 0 * LSZ, bhi + 1 * LSZ,
                                              zb, hb, 1);                    // [4] profiled
    scan_p1<<<p1_blocks, 256>>>((const float4*)zb, (const float4*)hb);
    scan_p2<<<p2_blocks, 256>>>();
    scan_p3_norm_fuse<<<p3_blocks, 512>>>(zb, hb, h1, pz1, ph1, 2);

    // ---- layer 1 (A tiles built by fused p3) ----
    apl_hmma_kernel<<<gpair, 256, SMEM_REQ>>>(a0, m0, a1, m1,
                                              bhi + 2 * LSZ, bhi + 3 * LSZ,
                                              zb, hb, 1);
    scan_p1<<<p1_blocks, 256>>>((const float4*)zb, (const float4*)hb);
    scan_p2<<<p2_blocks, 256>>>();
    scan_p3_norm_fuse<<<p3_blocks, 512>>>(zb, hb, h2, po, po, 1);

    // ---- output APL (A tiles built by fused p3) ----
    apl_hmma_kernel<<<gone, 256, SMEM_REQ>>>(a0, m0, a0, m0,
                                             bhi + 4 * LSZ, bhi + 4 * LSZ,
                                             out, out, 0);
}